// round 11
// baseline (speedup 1.0000x reference)
#include <cuda_runtime.h>
#include <cstddef>

#define IMG_H 512
#define IMG_W 512
#define IMGF  (IMG_H * IMG_W * 3)
#define TILE_W 64
#define TILE_H 32
#define NP_TOT 1024
#define OUTF_PER_B (NP_TOT * 768)

// Weight layout: 27 taps (wrow,dx,ci) x {co0,co1,co2,pad}; float2 at 4*tap is 8B-aligned.
__constant__ float c_wR[108];

// Output-linear permuted pos_emb with bias folded in (batch-independent), 3 MB.
__device__ float d_pe_perm[OUTF_PER_B];

// ---- prep: vectorized permute, 1 float4 per thread, bias folded ----
__global__ __launch_bounds__(256)
void pe_permute_kernel(const float* __restrict__ pos_emb,
                       const float* __restrict__ bias)
{
    const int j4 = blockIdx.x * 256 + threadIdx.x;     // < 196608
    const int np  = j4 / 192;
    const int rm4 = j4 - np * 192;
    const int r   = rm4 / 12;                          // row in patch
    const int k4  = rm4 - r * 12;                      // float4 within 48-float row
    const int gh  = ((np >> 5) << 4) + r;
    const int fc  = k4 / 3;                            // fine col within patch (0..3)
    const int sub = k4 - fc * 3;
    const int nf  = (gh >> 2) * 128 + ((np & 31) << 2) + fc;
    const int src4 = nf * 12 + (gh & 3) * 3 + sub;

    float4 v = ((const float4*)pos_emb)[src4];
    const float b0 = bias[0], b1 = bias[1], b2 = bias[2];
    // channel of component t: (k4 + t) % 3
    const int c0 = k4 % 3;
    const float bb[3] = { b0, b1, b2 };
    v.x += bb[c0];
    v.y += bb[(c0 + 1) % 3];
    v.z += bb[(c0 + 2) % 3];
    v.w += bb[c0];
    ((float4*)d_pe_perm)[j4] = v;
}

__device__ __forceinline__ void load_row_g(const float* __restrict__ Xb,
                                           int row_off, bool rvalid,
                                           bool zl, bool zr, float f[20])
{
#pragma unroll
    for (int j = 0; j < 5; j++) {
        float4 v = make_float4(0.f, 0.f, 0.f, 0.f);
        const int g = row_off + 4 * j;
        if (rvalid && g >= 0 && g + 3 < IMGF)
            v = *(const float4*)(Xb + g);
        f[4*j+0] = v.x; f[4*j+1] = v.y; f[4*j+2] = v.z; f[4*j+3] = v.w;
    }
    if (zl) { f[1]  = 0.f; f[2]  = 0.f; f[3]  = 0.f; }
    if (zr) { f[16] = 0.f; f[17] = 0.f; f[18] = 0.f; }
}

// Channel-paired conv row application: accp[x] packs (co0,co1), accs[x] is co2.
__device__ __forceinline__ void apply2(const float f[20],
                                       unsigned long long accp[4], float accs[4],
                                       const int wrow)
{
#pragma unroll
    for (int p = 0; p < 6; p++) {
#pragma unroll
        for (int ci = 0; ci < 3; ci++) {
            const float v = f[3*p + ci + 1];
            unsigned long long vv;
            asm("mov.b64 %0, {%1, %1};" : "=l"(vv) : "f"(v));
            const int xmin = (p >= 3) ? (p - 2) : 0;
            const int xmax = (p < 4) ? p : 3;
#pragma unroll
            for (int x = xmin; x <= xmax; x++) {
                const int dx  = p - x;
                const int tap = (wrow*3 + dx)*3 + ci;
                const unsigned long long w01 = *(const unsigned long long*)&c_wR[4*tap];
                const float w2 = c_wR[4*tap + 2];
                asm("fma.rn.f32x2 %0, %1, %2, %0;" : "+l"(accp[x]) : "l"(vv), "l"(w01));
                accs[x] = fmaf(v, w2, accs[x]);
            }
        }
    }
}

__global__ __launch_bounds__(256, 4)
void patchenc_v6_kernel(const float* __restrict__ X,
                        float* __restrict__ out)
{
    __shared__ float4 sout4[1536];   // 24 KB, output-ordered

    const int b  = blockIdx.z;
    const int h0 = blockIdx.y * TILE_H;
    const int w0 = blockIdx.x * TILE_W;
    const float* __restrict__ Xb = X + (size_t)b * IMGF;

    const int txq = threadIdx.x & 15;
    const int tyq = threadIdx.x >> 4;
    const int gh0 = h0 + 2 * tyq;

    const bool zl = (w0 == 0) && (txq == 0);
    const bool zr = (w0 == IMG_W - TILE_W) && (txq == 15);

    const int base_off = 3 * w0 + 12 * txq - 4;
    const int ROWF = 3 * IMG_W;

    unsigned long long ap0[4] = {0,0,0,0}, ap1[4] = {0,0,0,0};
    float as0[4] = {0,0,0,0}, as1[4] = {0,0,0,0};

    float f[20];
    {
        const int r = gh0 - 1;
        load_row_g(Xb, base_off + r * ROWF, r >= 0, zl, zr, f);
        apply2(f, ap0, as0, 0);
    }
    {
        load_row_g(Xb, base_off + gh0 * ROWF, true, zl, zr, f);
        apply2(f, ap0, as0, 1);
        apply2(f, ap1, as1, 0);
    }
    {
        load_row_g(Xb, base_off + (gh0 + 1) * ROWF, true, zl, zr, f);
        apply2(f, ap0, as0, 2);
        apply2(f, ap1, as1, 1);
    }
    {
        const int r = gh0 + 2;
        load_row_g(Xb, base_off + r * ROWF, r < IMG_H, zl, zr, f);
        apply2(f, ap1, as1, 2);
    }

    // ---- stage into output-ordered smem ----
    const int band = tyq >> 3;
    const int pch  = txq >> 2;
#pragma unroll
    for (int k = 0; k < 2; k++) {
        const unsigned long long* ap = (k == 0) ? ap0 : ap1;
        const float* as = (k == 0) ? as0 : as1;
        float a[12];
#pragma unroll
        for (int x = 0; x < 4; x++) {
            float lo, hi;
            asm("mov.b64 {%0, %1}, %2;" : "=f"(lo), "=f"(hi) : "l"(ap[x]));
            a[x*3+0] = lo; a[x*3+1] = hi; a[x*3+2] = as[x];
        }
        const int gh = gh0 + k;
        float4* so = &sout4[band * 768 + pch * 192 + (gh & 15) * 12 + (txq & 3) * 3];
        so[0] = make_float4(a[0], a[1],  a[2],  a[3]);
        so[1] = make_float4(a[4], a[5],  a[6],  a[7]);
        so[2] = make_float4(a[8], a[9],  a[10], a[11]);
    }

    __syncthreads();

    // ---- linear copy-out fused with linear PE(+bias) add ----
    const int npb0 = (h0 >> 4) * 32 + (w0 >> 4);
    const float4* pe4 = (const float4*)d_pe_perm;
    float4* ob = (float4*)out + (size_t)b * (OUTF_PER_B / 4);

#pragma unroll
    for (int k = 0; k < 6; k++) {
        const int v  = threadIdx.x + k * 256;        // 0..1535
        const int bd = (v >= 768) ? 1 : 0;
        const int rm = v - bd * 768;
        const size_t g4 = (size_t)(npb0 + bd * 32) * 192 + rm;
        float4 s = sout4[v];
        float4 p = pe4[g4];
        ob[g4] = make_float4(s.x + p.x, s.y + p.y, s.z + p.z, s.w + p.w);
    }
}

extern "C" void kernel_launch(void* const* d_in, const int* in_sizes, int n_in,
                              void* d_out, int out_size)
{
    const float* X  = (const float*)d_in[0];
    const float* Kw = (const float*)d_in[1];   // 81 floats, [tap][co] packed by 12B
    const float* Bb = (const float*)d_in[2];
    const float* PE = (const float*)d_in[3];

    // Re-layout weights into 16B-strided taps: one 2D D2D memcpy node.
    void* wR_addr = nullptr;
    cudaGetSymbolAddress(&wR_addr, c_wR);
    cudaMemcpy2DAsync(wR_addr, 16 /*dpitch*/, Kw, 12 /*spitch*/,
                      12 /*width bytes*/, 27 /*rows*/,
                      cudaMemcpyDeviceToDevice, 0);

    // PE permute + bias fold: 196608 float4
    pe_permute_kernel<<<768, 256>>>(PE, Bb);

    dim3 grid(IMG_W / TILE_W, IMG_H / TILE_H, 32);
    patchenc_v6_kernel<<<grid, 256>>>(X, (float*)d_out);
}